// round 14
// baseline (speedup 1.0000x reference)
#include <cuda_runtime.h>
#include <math.h>

typedef unsigned long long ull;

// ---------------------------------------------------------------------------
// Arena: f1(32M1) ps1(3M1) ps2(3M2) f2(128M2) agg3(128G) glo1/glo2 packs
#define MAXN (1u << 20)
static __device__ float g_arena[167ull * MAXN + 262144ull];

__device__ __forceinline__ float celu1(float x) { return x > 0.f ? x : expm1f(x); }
__device__ __forceinline__ void ffma2(ull& d, ull a, ull b) {
    asm("fma.rn.f32x2 %0, %1, %2, %0;" : "+l"(d) : "l"(a), "l"(b));
}
__device__ __forceinline__ float ull_sum(ull v) {
    float a, b;
    asm("mov.b64 {%0, %1}, %2;" : "=f"(a), "=f"(b) : "l"(v));
    return a + b;
}
__device__ __forceinline__ float ull_max(ull v) {
    float a, b;
    asm("mov.b64 {%0, %1}, %2;" : "=f"(a), "=f"(b) : "l"(v));
    return fmaxf(a, b);
}
__device__ __forceinline__ ull ld2(const float* p) { return *(const ull*)p; }
__device__ __forceinline__ ull pk2(float a, float b) {
    ull r;
    asm("mov.b64 %0, {%1, %2};" : "=l"(r) : "f"(a), "f"(b));
    return r;
}

// ------------------- weight pre-pack: k-paired interleave -------------------
__device__ __forceinline__ void packw(float* dst, const float* src, int K, int C, int t) {
    int k2 = t / (2 * C);
    int col = t - k2 * 2 * C;
    int j = col >> 1;
    int k = 2 * k2 + (col & 1);
    dst[t] = (k < K) ? src[k * C + j] : 0.0f;
}
// packs total 126272 floats; then zero agg3 (128G floats) via float4
__global__ void k_prep(const float* __restrict__ W1l, const float* __restrict__ W1g,
                       const float* __restrict__ W2l, const float* __restrict__ W2g,
                       const float* __restrict__ W3g, const float* __restrict__ Wlin,
                       const float* __restrict__ W3l,
                       float* Wp1l, float* Wp1g, float* Wp2l, float* Wp2g,
                       float* Wp3g, float* Wplin, float* Wp3l,
                       float* agg3, int G) {
    int t = blockIdx.x * blockDim.x + threadIdx.x;
    if (t < 64) packw(Wp1l, W1l, 4, 16, t);
    else if (t < 576) packw(Wp1g, W1g, 16, 32, t - 64);
    else if (t < 2880) packw(Wp2l, W2l, 35, 64, t - 576);
    else if (t < 11072) packw(Wp2g, W2g, 64, 128, t - 2880);
    else if (t < 43840) packw(Wp3g, W3g, 128, 256, t - 11072);
    else if (t < 109376) packw(Wplin, Wlin, 256, 256, t - 43840);
    else if (t < 126272) packw(Wp3l, W3l, 131, 128, t - 109376);
    else {
        int z = t - 126272;
        if (z < 32 * G)
            *(float4*)&agg3[4 * z] = make_float4(0.f, 0.f, 0.f, 0.f);
    }
}

// --------- block-wide exclusive scan of 1024 ints with 512 threads ----------
__device__ __forceinline__ void scan1024_512(const int* cnt, int* start, int* wsum,
                                             int tid) {
    int t2 = tid * 2;
    int v0 = cnt[t2], v1 = cnt[t2 + 1];
    int s1 = v0 + v1;
    int lane = tid & 31, wid = tid >> 5;
    int x = s1;
#pragma unroll
    for (int o = 1; o < 32; o <<= 1) {
        int y = __shfl_up_sync(0xffffffffu, x, o);
        if (lane >= o) x += y;
    }
    if (lane == 31) wsum[wid] = x;
    __syncthreads();
    if (tid == 0) {
        int a = 0;
        for (int w = 0; w < 16; w++) { int tt = wsum[w]; wsum[w] = a; a += tt; }
    }
    __syncthreads();
    int e = wsum[wid] + x - s1;
    start[t2] = e;
    start[t2 + 1] = e + v0;
}

// ---------------------------------------------------------------------------
// Stage 1: one block (512 thr) per glimpse. Vectorized point staging; CSR over
// cluster1 in smem; owner-computes: ps1 mean, msg1 (4->16, j-outer 2-pt chunks)
// relu+max, f1 = celu(.@W1g) (16->32).
// ---------------------------------------------------------------------------
__global__ void __launch_bounds__(512) k_stage1(
    const float* __restrict__ rgb, const float* __restrict__ pos,
    const int* __restrict__ cl1, const float* __restrict__ Wp1l,
    const float* __restrict__ b1l, const float* __restrict__ Wp1g,
    const float* __restrict__ b1g, float* __restrict__ ps1, float* __restrict__ f1,
    int* __restrict__ glo1, int P, int G) {
    __shared__ __align__(16) float4 pts[1024];
    __shared__ __align__(16) float posraw[3072];
    __shared__ __align__(16) float rgbs[1024];
    __shared__ int cls[1024];
    __shared__ int cnt[1024];
    __shared__ int start[1024];
    __shared__ int fill[1024];
    __shared__ int csr[1024];
    __shared__ __align__(16) float wl[64];
    __shared__ __align__(16) float wg[512];
    __shared__ float blv[16], bgv[32];
    __shared__ int wsum[16];
    __shared__ int s_lo, s_hi;
    int tid = threadIdx.x, g = blockIdx.x;
    if (tid == 0) { s_lo = 0x7fffffff; s_hi = -1; }
    if (tid < 64) wl[tid] = Wp1l[tid];
    wg[tid] = Wp1g[tid];
    if (tid < 16) blv[tid] = b1l[tid];
    if (tid < 32) bgv[tid] = b1g[tid];
    for (int t = tid; t < 1024; t += 512) { cnt[t] = 0; fill[t] = 0; }
    __syncthreads();
    int lmin = 0x7fffffff, lmax = -1;
    if ((P & 3) == 0) {
        // vectorized staging: pos (3P/4 float4), rgb (P/4), cl1 (P/4 int4)
        const float4* pos4 = (const float4*)(pos + 3ull * g * P);
        for (int t = tid; t < 3 * P / 4; t += 512) ((float4*)posraw)[t] = pos4[t];
        const float4* rgb4 = (const float4*)(rgb + (size_t)g * P);
        for (int t = tid; t < P / 4; t += 512) ((float4*)rgbs)[t] = rgb4[t];
        const int4* cl4 = (const int4*)(cl1 + (size_t)g * P);
        for (int t = tid; t < P / 4; t += 512) {
            int4 c4 = cl4[t];
            cls[4 * t + 0] = c4.x;
            cls[4 * t + 1] = c4.y;
            cls[4 * t + 2] = c4.z;
            cls[4 * t + 3] = c4.w;
            lmin = min(lmin, min(min(c4.x, c4.y), min(c4.z, c4.w)));
            lmax = max(lmax, max(max(c4.x, c4.y), max(c4.z, c4.w)));
        }
        __syncthreads();
        for (int i = tid; i < P; i += 512)
            pts[i] = make_float4(posraw[3 * i], posraw[3 * i + 1], posraw[3 * i + 2],
                                 rgbs[i]);
    } else {
        for (int i = tid; i < P; i += 512) {
            int gi = g * P + i;
            pts[i] = make_float4(pos[3 * gi], pos[3 * gi + 1], pos[3 * gi + 2], rgb[gi]);
            int c = cl1[gi];
            cls[i] = c;
            lmin = min(lmin, c);
            lmax = max(lmax, c);
        }
    }
    atomicMin(&s_lo, lmin);
    atomicMax(&s_hi, lmax);
    __syncthreads();
    int lo = s_lo, W = s_hi - lo + 1;
    for (int i = tid; i < P; i += 512) {
        int l = cls[i] - lo;
        cls[i] = l;
        atomicAdd(&cnt[l], 1);
    }
    __syncthreads();
    scan1024_512(cnt, start, wsum, tid);
    __syncthreads();
    for (int i = tid; i < P; i += 512) {
        int l = cls[i];
        csr[start[l] + atomicAdd(&fill[l], 1)] = i;
    }
    __syncthreads();
    for (int v = tid; v < W; v += 512) {
        int s = start[v], c = cnt[v];
        float sx = 0.f, sy = 0.f, sz = 0.f;
        for (int q = 0; q < c; q++) {
            float4 p = pts[csr[s + q]];
            sx += p.x; sy += p.y; sz += p.z;
        }
        float inv = 1.0f / (float)c;
        float mx = sx * inv, my = sy * inv, mz = sz * inv;
        int vg = lo + v;
        ps1[3 * vg] = mx; ps1[3 * vg + 1] = my; ps1[3 * vg + 2] = mz;
        // msg1: j-outer, 2-point register chunks (dup last if odd: max-idempotent)
        float m[16];
#pragma unroll
        for (int j = 0; j < 16; j++) m[j] = 0.f;
        for (int q0 = 0; q0 < c; q0 += 2) {
            int qb = (q0 + 1 < c) ? q0 + 1 : q0;
            float4 pa = pts[csr[s + q0]];
            float4 pb = pts[csr[s + qb]];
            ull a0 = pk2(pa.w, pa.x - mx), a1 = pk2(pa.y - my, pa.z - mz);
            ull b0 = pk2(pb.w, pb.x - mx), b1 = pk2(pb.y - my, pb.z - mz);
#pragma unroll
            for (int j = 0; j < 16; j++) {
                ull w0 = ld2(&wl[2 * j]);
                ull w1 = ld2(&wl[32 + 2 * j]);
                ull accA = 0ull, accB = 0ull;
                ffma2(accA, a0, w0);
                ffma2(accA, a1, w1);
                ffma2(accB, b0, w0);
                ffma2(accB, b1, w1);
                float r = fmaxf(ull_sum(accA), ull_sum(accB)) + blv[j];
                m[j] = fmaxf(m[j], fmaxf(r, 0.f));
            }
        }
        ull mp[8];
#pragma unroll
        for (int k2 = 0; k2 < 8; k2++) mp[k2] = pk2(m[2 * k2], m[2 * k2 + 1]);
        float* f1row = f1 + (size_t)vg * 32;
#pragma unroll
        for (int jo = 0; jo < 32; jo += 4) {
            float4 o4;
            float* po = (float*)&o4;
#pragma unroll
            for (int u = 0; u < 4; u++) {
                int j = jo + u;
                ull acc = 0ull;
#pragma unroll
                for (int k2 = 0; k2 < 8; k2++) ffma2(acc, mp[k2], ld2(&wg[k2 * 64 + 2 * j]));
                po[u] = celu1(ull_sum(acc) + bgv[j]);
            }
            *(float4*)(f1row + jo) = o4;
        }
    }
    if (tid == 0) {
        glo1[g] = lo;
        if (g == G - 1) glo1[G] = lo + W;
    }
}

// ---------------------------------------------------------------------------
// Stage 2 (R13 proven): one block (512 thr / 16 warps) per glimpse. CSR over
// cluster2; per-warp owner-computes msg2 (35->64, 4-edge batches, FLOAT4
// staging) relu+max, then f2 = celu(.@W2g). Writes ps2, f2.
// ---------------------------------------------------------------------------
#define SMB_INTS (5 * 1024 + 64 + 16 + 2)
#define SMB_FLOATS (2304 + 8192 + 64 + 128 + 3072 + 16 * 144 + 16 * 256)
#define SMB_BYTES ((SMB_FLOATS + SMB_INTS) * 4)
__global__ void __launch_bounds__(512) k_stage2(
    const float* __restrict__ ps1, const float* __restrict__ f1,
    const int* __restrict__ cl2, const int* __restrict__ glo1,
    const float* __restrict__ Wp2l, const float* __restrict__ b2l,
    const float* __restrict__ Wp2g, const float* __restrict__ b2g,
    float* __restrict__ ps2, float* __restrict__ f2, int* __restrict__ glo2, int G) {
    extern __shared__ float sm[];
    float* Wl = sm;                     // 2304
    float* Wg = Wl + 2304;              // 8192
    float* bl = Wg + 8192;              // 64
    float* bg = bl + 64;                // 128
    float* ps2loc = bg + 128;           // 3072
    float* ins = ps2loc + 3072;         // 16*144
    float* aggs = ins + 16 * 144;       // 16*256
    int* cls = (int*)(aggs + 16 * 256); // 1024
    int* cnt = cls + 1024;
    int* start = cnt + 1024;
    int* fill = start + 1024;
    int* csr = fill + 1024;
    int* vpend = csr + 1024;            // 64
    int* wsum = vpend + 64;             // 16
    int* s_lohi = wsum + 16;            // 2
    int tid = threadIdx.x, g = blockIdx.x;
    int lane = tid & 31, wid = tid >> 5;
    for (int t = tid; t < 2304; t += 512) Wl[t] = Wp2l[t];
    for (int t = tid; t < 8192; t += 512) Wg[t] = Wp2g[t];
    if (tid < 64) bl[tid] = b2l[tid];
    if (tid < 128) bg[tid] = b2g[tid];
    if (tid == 0) { s_lohi[0] = 0x7fffffff; s_lohi[1] = -1; }
    for (int t = tid; t < 1024; t += 512) { cnt[t] = 0; fill[t] = 0; }
    __syncthreads();
    int L = glo1[g], W1 = glo1[g + 1] - L;
    int lmin = 0x7fffffff, lmax = -1;
    for (int i = tid; i < W1; i += 512) {
        int c = cl2[L + i];
        cls[i] = c;
        lmin = min(lmin, c);
        lmax = max(lmax, c);
    }
    atomicMin(&s_lohi[0], lmin);
    atomicMax(&s_lohi[1], lmax);
    __syncthreads();
    int lo2 = s_lohi[0], W2 = s_lohi[1] - lo2 + 1;
    for (int i = tid; i < W1; i += 512) {
        int l = cls[i] - lo2;
        cls[i] = l;
        atomicAdd(&cnt[l], 1);
    }
    __syncthreads();
    scan1024_512(cnt, start, wsum, tid);
    __syncthreads();
    for (int i = tid; i < W1; i += 512) {
        int l = cls[i];
        csr[start[l] + atomicAdd(&fill[l], 1)] = i;
    }
    __syncthreads();
    for (int v = tid; v < W2; v += 512) {
        int s = start[v], c = cnt[v];
        float sx = 0.f, sy = 0.f, sz = 0.f;
        for (int q = 0; q < c; q++) {
            int e = L + csr[s + q];
            sx += ps1[3 * e]; sy += ps1[3 * e + 1]; sz += ps1[3 * e + 2];
        }
        float inv = 1.0f / (float)c;
        sx *= inv; sy *= inv; sz *= inv;
        ps2loc[3 * v] = sx; ps2loc[3 * v + 1] = sy; ps2loc[3 * v + 2] = sz;
        int vg = lo2 + v;
        ps2[3 * vg] = sx; ps2[3 * vg + 1] = sy; ps2[3 * vg + 2] = sz;
    }
    __syncthreads();
    float* insW = ins + wid * 144;
    float* aggW = aggs + wid * 256;
    int* vpW = vpend + wid * 4;
    int npend = 0;
    int se = lane >> 3, sq = lane & 7;
    int re = lane >> 2, rk = lane & 3;
    for (int v = wid; v < W2; v += 16) {
        int s = start[v], c = cnt[v];
        float m0 = 0.f, m1 = 0.f;
        for (int base = 0; base < c; base += 4) {
            __syncwarp();
            {
                int ee = base + se;
                if (ee >= c) ee = c - 1;
                int eg = L + csr[s + ee];
                *(float4*)&insW[se * 36 + 4 * sq] =
                    *(const float4*)&f1[(size_t)eg * 32 + 4 * sq];
                if (lane < 16) {
                    int ee2 = base + re;
                    if (ee2 >= c) ee2 = c - 1;
                    int eg2 = L + csr[s + ee2];
                    float val = 0.f;
                    if (rk < 3) val = ps1[3 * eg2 + rk] - ps2loc[3 * v + rk];
                    insW[re * 36 + 32 + rk] = val;
                }
            }
            __syncwarp();
            ull a00 = 0, a01 = 0, a02 = 0, a03 = 0, a10 = 0, a11 = 0, a12 = 0, a13 = 0;
#pragma unroll
            for (int k2 = 0; k2 < 18; k2++) {
                ull w0 = ld2(&Wl[k2 * 128 + 2 * lane]);
                ull w1 = ld2(&Wl[k2 * 128 + 64 + 2 * lane]);
                ull x0 = ld2(&insW[0 * 36 + 2 * k2]);
                ull x1 = ld2(&insW[1 * 36 + 2 * k2]);
                ull x2 = ld2(&insW[2 * 36 + 2 * k2]);
                ull x3 = ld2(&insW[3 * 36 + 2 * k2]);
                ffma2(a00, x0, w0); ffma2(a01, x1, w0); ffma2(a02, x2, w0); ffma2(a03, x3, w0);
                ffma2(a10, x0, w1); ffma2(a11, x1, w1); ffma2(a12, x2, w1); ffma2(a13, x3, w1);
            }
            float b0 = bl[lane], b1 = bl[lane + 32];
            m0 = fmaxf(m0, fmaxf(ull_sum(a00) + b0, 0.f));
            m0 = fmaxf(m0, fmaxf(ull_sum(a01) + b0, 0.f));
            m0 = fmaxf(m0, fmaxf(ull_sum(a02) + b0, 0.f));
            m0 = fmaxf(m0, fmaxf(ull_sum(a03) + b0, 0.f));
            m1 = fmaxf(m1, fmaxf(ull_sum(a10) + b1, 0.f));
            m1 = fmaxf(m1, fmaxf(ull_sum(a11) + b1, 0.f));
            m1 = fmaxf(m1, fmaxf(ull_sum(a12) + b1, 0.f));
            m1 = fmaxf(m1, fmaxf(ull_sum(a13) + b1, 0.f));
        }
        __syncwarp();
        aggW[npend * 64 + lane] = m0;
        aggW[npend * 64 + 32 + lane] = m1;
        vpW[npend] = lo2 + v;
        npend++;
        if (npend == 4) {
            __syncwarp();
#pragma unroll
            for (int u = 0; u < 4; u++) {
                int j = lane + 32 * u;
                ull acc0 = 0, acc1 = 0, acc2 = 0, acc3 = 0;
#pragma unroll 8
                for (int k2 = 0; k2 < 32; k2++) {
                    ull w = ld2(&Wg[k2 * 256 + 2 * j]);
                    ffma2(acc0, ld2(&aggW[0 * 64 + 2 * k2]), w);
                    ffma2(acc1, ld2(&aggW[1 * 64 + 2 * k2]), w);
                    ffma2(acc2, ld2(&aggW[2 * 64 + 2 * k2]), w);
                    ffma2(acc3, ld2(&aggW[3 * 64 + 2 * k2]), w);
                }
                float bb = bg[j];
                f2[(size_t)vpW[0] * 128 + j] = celu1(ull_sum(acc0) + bb);
                f2[(size_t)vpW[1] * 128 + j] = celu1(ull_sum(acc1) + bb);
                f2[(size_t)vpW[2] * 128 + j] = celu1(ull_sum(acc2) + bb);
                f2[(size_t)vpW[3] * 128 + j] = celu1(ull_sum(acc3) + bb);
            }
            __syncwarp();
            npend = 0;
        }
    }
    if (npend) {
        __syncwarp();
#pragma unroll
        for (int u = 0; u < 4; u++) {
            int j = lane + 32 * u;
            ull acc0 = 0, acc1 = 0, acc2 = 0;
#pragma unroll 8
            for (int k2 = 0; k2 < 32; k2++) {
                ull w = ld2(&Wg[k2 * 256 + 2 * j]);
                ffma2(acc0, ld2(&aggW[0 * 64 + 2 * k2]), w);
                ffma2(acc1, ld2(&aggW[1 * 64 + 2 * k2]), w);
                ffma2(acc2, ld2(&aggW[2 * 64 + 2 * k2]), w);
            }
            float bb = bg[j];
            if (npend > 0) f2[(size_t)vpW[0] * 128 + j] = celu1(ull_sum(acc0) + bb);
            if (npend > 1) f2[(size_t)vpW[1] * 128 + j] = celu1(ull_sum(acc1) + bb);
            if (npend > 2) f2[(size_t)vpW[2] * 128 + j] = celu1(ull_sum(acc2) + bb);
        }
    }
    if (tid == 0) {
        glo2[g] = lo2;
        if (g == G - 1) glo2[G] = lo2 + W2;
    }
}

// ---------------------------------------------------------------------------
// msg3 v3 (PROVEN, FINAL): persistent grid-stride, 128-edge tiles, 512 thr,
// plain staging. k-paired reduction, 8 consecutive edges x 4 j.
// ---------------------------------------------------------------------------
#define MSG3_ROW 136
#define SM_MSG3_FLOATS (16896 + 128 * MSG3_ROW + 128)
#define SM_MSG3_BYTES (SM_MSG3_FLOATS * 4 + 128 * 4)
__global__ void __launch_bounds__(512) k_msg3(
    const float* __restrict__ f2, const float* __restrict__ ps2,
    const int* __restrict__ bt2, const float* __restrict__ Wp3l,
    const float* __restrict__ b3l, float* __restrict__ agg3, int n) {
    extern __shared__ float sm[];
    float* Wsm = sm;                         // 66*256 = 16896 (k-paired)
    float* ins = Wsm + 16896;                // 128*136
    float* bsm = ins + 128 * MSG3_ROW;       // 128
    int* slots = (int*)(bsm + 128);          // 128
    int tid = threadIdx.x;
    int lane = tid & 31, eg = tid >> 5;      // eg 0..15: edges eg*8..eg*8+7
    for (int t = tid; t < 4224; t += 512)
        *(float4*)&Wsm[4 * t] = *(const float4*)&Wp3l[4 * t];
    if (tid < 128) bsm[tid] = b3l[tid];
    int ntiles = (n + 127) >> 7;
    for (int tile = blockIdx.x; tile < ntiles; tile += gridDim.x) {
        int base = tile << 7;
        __syncthreads();
        for (int idx = tid; idx < 128 * 32; idx += 512) {
            int e = idx >> 5, q = idx & 31;
            int i = base + e;
            if (i >= n) i = n - 1;
            *(float4*)&ins[e * MSG3_ROW + 4 * q] = *(const float4*)&f2[(size_t)i * 128 + 4 * q];
        }
        if (tid < 128) {
            int e = tid;
            int i = base + e;
            if (i >= n) i = n - 1;
            ins[e * MSG3_ROW + 128] = ps2[3 * i];
            ins[e * MSG3_ROW + 129] = ps2[3 * i + 1];
            ins[e * MSG3_ROW + 130] = ps2[3 * i + 2];
            ins[e * MSG3_ROW + 131] = 0.f;
            slots[e] = bt2[i];
        }
        __syncthreads();
        const float* insE = ins + eg * 8 * MSG3_ROW;
        ull acc[8][4];
#pragma unroll
        for (int i = 0; i < 8; i++)
#pragma unroll
            for (int u = 0; u < 4; u++) acc[i][u] = 0ull;
#pragma unroll 2
        for (int k2 = 0; k2 < 66; k2++) {
            ull x[8];
#pragma unroll
            for (int i = 0; i < 8; i++) x[i] = ld2(&insE[i * MSG3_ROW + 2 * k2]);
            const float* wr = &Wsm[k2 * 256 + 2 * lane];
#pragma unroll
            for (int u = 0; u < 4; u++) {
                ull w = ld2(wr + 64 * u);
#pragma unroll
                for (int i = 0; i < 8; i++) ffma2(acc[i][u], x[i], w);
            }
        }
        int gs[8];
#pragma unroll
        for (int i = 0; i < 8; i++) gs[i] = slots[eg * 8 + i];
#pragma unroll
        for (int u = 0; u < 4; u++) {
            int j = lane + 32 * u;
            float bb = bsm[j];
            float v[8];
#pragma unroll
            for (int i = 0; i < 8; i++) v[i] = fmaxf(ull_sum(acc[i][u]) + bb, 0.f);
            int i = 0;
            while (i < 8) {
                int g = gs[i];
                float mv = v[i];
                int f = i + 1;
                while (f < 8 && gs[f] == g) { mv = fmaxf(mv, v[f]); f++; }
                atomicMax((unsigned int*)&agg3[(size_t)g * 128 + j], __float_as_uint(mv));
                i = f;
            }
        }
    }
}

// ------------- fused f3 + head: 8 glimpses/block, 256 threads ---------------
__global__ void __launch_bounds__(256) k_f3head(
    const float* __restrict__ agg3, const float* __restrict__ Wp3g,
    const float* __restrict__ b3g, const float* __restrict__ Wplin,
    const float* __restrict__ blin, const float* __restrict__ eps,
    float* __restrict__ f3, float* __restrict__ out, int G) {
    __shared__ __align__(16) float a3[8 * 128];
    __shared__ __align__(16) float fs[8 * 256];
    __shared__ float sig_s[8 * 128];
    int tid = threadIdx.x;
    int g0 = blockIdx.x * 8;
    {
        int e = tid >> 5, kq = tid & 31;
        int g = g0 + e;
        float4 v = make_float4(0.f, 0.f, 0.f, 0.f);
        if (g < G) v = *(const float4*)&agg3[(size_t)g * 128 + 4 * kq];
        *(float4*)&a3[e * 128 + 4 * kq] = v;
    }
    __syncthreads();
    {
        ull acc[8];
#pragma unroll
        for (int e = 0; e < 8; e++) acc[e] = 0ull;
#pragma unroll 4
        for (int k2 = 0; k2 < 64; k2++) {
            ull w = ld2(&Wp3g[k2 * 512 + 2 * tid]);
#pragma unroll
            for (int e = 0; e < 8; e++) ffma2(acc[e], ld2(&a3[e * 128 + 2 * k2]), w);
        }
        float bb = __ldg(&b3g[tid]);
#pragma unroll
        for (int e = 0; e < 8; e++) {
            int g = g0 + e;
            float vv = celu1(ull_sum(acc[e]) + bb);
            fs[e * 256 + tid] = vv;
            if (g < G) f3[(size_t)g * 256 + tid] = vv;
        }
    }
    __syncthreads();
    ull acc[8];
#pragma unroll
    for (int e = 0; e < 8; e++) acc[e] = 0ull;
#pragma unroll 4
    for (int k2 = 0; k2 < 128; k2++) {
        ull w = ld2(&Wplin[k2 * 512 + 2 * tid]);
#pragma unroll
        for (int e = 0; e < 8; e++) ffma2(acc[e], ld2(&fs[e * 256 + 2 * k2]), w);
    }
    float bb = __ldg(&blin[tid]);
    float val[8];
#pragma unroll
    for (int e = 0; e < 8; e++) val[e] = ull_sum(acc[e]) + bb;
    if (tid >= 128) {
        int j = tid - 128;
#pragma unroll
        for (int e = 0; e < 8; e++) {
            float s = val[e];
            float sg = fmaxf(s, 0.0f) + log1pf(expf(-fabsf(s)));
            sig_s[e * 128 + j] = sg;
            int g = g0 + e;
            if (g < G) out[(size_t)G * 256 + (size_t)g * 128 + j] = sg;
        }
    }
    __syncthreads();
    if (tid < 128) {
        int j = tid;
#pragma unroll
        for (int e = 0; e < 8; e++) {
            int g = g0 + e;
            if (g >= G) continue;
            float mu = val[e];
            float sg = sig_s[e * 128 + j];
            float z = fmaf(sg, eps[(size_t)g * 128 + j], mu);
            out[(size_t)G * 128 + (size_t)g * 128 + j] = mu;
            if (j < 64) out[(size_t)g * 64 + j] = z;
            else out[(size_t)G * 64 + (size_t)g * 64 + (j - 64)] = z;
        }
    }
}

// ---------------------------------------------------------------------------
extern "C" void kernel_launch(void* const* d_in, const int* in_sizes, int n_in,
                              void* d_out, int out_size) {
    const float* rgb = (const float*)d_in[0];
    const float* pos = (const float*)d_in[1];
    const float* W1l = (const float*)d_in[3];
    const float* b1l = (const float*)d_in[4];
    const float* W1g = (const float*)d_in[5];
    const float* b1g = (const float*)d_in[6];
    const float* W2l = (const float*)d_in[7];
    const float* b2l = (const float*)d_in[8];
    const float* W2g = (const float*)d_in[9];
    const float* b2g = (const float*)d_in[10];
    const float* W3l = (const float*)d_in[11];
    const float* b3l = (const float*)d_in[12];
    const float* W3g = (const float*)d_in[13];
    const float* b3g = (const float*)d_in[14];
    const float* Wlin = (const float*)d_in[15];
    const float* blin = (const float*)d_in[16];
    const float* eps = (const float*)d_in[17];
    const int* cl1 = (const int*)d_in[19];
    const int* cl2 = (const int*)d_in[20];
    const int* bt2 = (const int*)d_in[21];

    int N = in_sizes[0];
    int G = in_sizes[2] / 3;
    int M1 = in_sizes[20];
    int M2 = in_sizes[21];
    int P = N / G;

    float* A = nullptr;
    cudaGetSymbolAddress((void**)&A, g_arena);
    size_t o = 0;
    float* f1 = A + o;   o += 32ull * M1;       o = (o + 31) & ~31ull;
    float* ps1 = A + o;  o += 3ull * M1;        o = (o + 31) & ~31ull;
    float* ps2 = A + o;  o += 3ull * M2;        o = (o + 31) & ~31ull;
    float* f2 = A + o;   o += 128ull * M2;      o = (o + 31) & ~31ull;
    float* agg3 = A + o; o += 128ull * G;       o = (o + 31) & ~31ull;
    int* glo1 = (int*)(A + o); o += (size_t)G + 32; o = (o + 31) & ~31ull;
    int* glo2 = (int*)(A + o); o += (size_t)G + 32; o = (o + 31) & ~31ull;
    float* Wp1l = A + o;  o += 64;
    float* Wp1g = A + o;  o += 512;
    float* Wp2l = A + o;  o += 2304;
    float* Wp2g = A + o;  o += 8192;
    float* Wp3g = A + o;  o += 32768;
    float* Wplin = A + o; o += 65536;
    float* Wp3l = A + o;  o += 16896;

    float* out = (float*)d_out;
    float* f3 = out + (size_t)G * 384;

    k_prep<<<(126272 + 32 * G + 255) / 256, 256>>>(W1l, W1g, W2l, W2g, W3g, Wlin, W3l,
                                                   Wp1l, Wp1g, Wp2l, Wp2g, Wp3g,
                                                   Wplin, Wp3l, agg3, G);

    k_stage1<<<G, 512>>>(rgb, pos, cl1, Wp1l, b1l, Wp1g, b1g, ps1, f1, glo1, P, G);

    cudaFuncSetAttribute(k_stage2, cudaFuncAttributeMaxDynamicSharedMemorySize, SMB_BYTES);
    k_stage2<<<G, 512, SMB_BYTES>>>(ps1, f1, cl2, glo1, Wp2l, b2l, Wp2g, b2g,
                                    ps2, f2, glo2, G);

    cudaFuncSetAttribute(k_msg3, cudaFuncAttributeMaxDynamicSharedMemorySize,
                         SM_MSG3_BYTES);
    k_msg3<<<148, 512, SM_MSG3_BYTES>>>(f2, ps2, bt2, Wp3l, b3l, agg3, M2);

    k_f3head<<<(G + 7) / 8, 256>>>(agg3, Wp3g, b3g, Wplin, blin, eps, f3, out, G);
}

// round 15
// speedup vs baseline: 1.0178x; 1.0178x over previous
#include <cuda_runtime.h>
#include <math.h>

typedef unsigned long long ull;

// ---------------------------------------------------------------------------
// Arena: f1(32M1) ps1(3M1) ps2(3M2) f2(128M2) agg3(128G) glo1/glo2 packs
#define MAXN (1u << 20)
static __device__ float g_arena[167ull * MAXN + 262144ull];

__device__ __forceinline__ float celu1(float x) { return x > 0.f ? x : expm1f(x); }
__device__ __forceinline__ void ffma2(ull& d, ull a, ull b) {
    asm("fma.rn.f32x2 %0, %1, %2, %0;" : "+l"(d) : "l"(a), "l"(b));
}
__device__ __forceinline__ float ull_sum(ull v) {
    float a, b;
    asm("mov.b64 {%0, %1}, %2;" : "=f"(a), "=f"(b) : "l"(v));
    return a + b;
}
__device__ __forceinline__ ull ld2(const float* p) { return *(const ull*)p; }
__device__ __forceinline__ ull pk2(float a, float b) {
    ull r;
    asm("mov.b64 %0, {%1, %2};" : "=l"(r) : "f"(a), "f"(b));
    return r;
}

// ------------------- weight pre-pack: k-paired interleave -------------------
__device__ __forceinline__ void packw(float* dst, const float* src, int K, int C, int t) {
    int k2 = t / (2 * C);
    int col = t - k2 * 2 * C;
    int j = col >> 1;
    int k = 2 * k2 + (col & 1);
    dst[t] = (k < K) ? src[k * C + j] : 0.0f;
}
// packs total 126272 floats; then zero agg3 (128G floats) via float4
__global__ void k_prep(const float* __restrict__ W1l, const float* __restrict__ W1g,
                       const float* __restrict__ W2l, const float* __restrict__ W2g,
                       const float* __restrict__ W3g, const float* __restrict__ Wlin,
                       const float* __restrict__ W3l,
                       float* Wp1l, float* Wp1g, float* Wp2l, float* Wp2g,
                       float* Wp3g, float* Wplin, float* Wp3l,
                       float* agg3, int G) {
    int t = blockIdx.x * blockDim.x + threadIdx.x;
    if (t < 64) packw(Wp1l, W1l, 4, 16, t);
    else if (t < 576) packw(Wp1g, W1g, 16, 32, t - 64);
    else if (t < 2880) packw(Wp2l, W2l, 35, 64, t - 576);
    else if (t < 11072) packw(Wp2g, W2g, 64, 128, t - 2880);
    else if (t < 43840) packw(Wp3g, W3g, 128, 256, t - 11072);
    else if (t < 109376) packw(Wplin, Wlin, 256, 256, t - 43840);
    else if (t < 126272) packw(Wp3l, W3l, 131, 128, t - 109376);
    else {
        int z = t - 126272;
        if (z < 32 * G)
            *(float4*)&agg3[4 * z] = make_float4(0.f, 0.f, 0.f, 0.f);
    }
}

// --------- block-wide exclusive scan of 1024 ints with 512 threads ----------
__device__ __forceinline__ void scan1024_512(const int* cnt, int* start, int* wsum,
                                             int tid) {
    int t2 = tid * 2;
    int v0 = cnt[t2], v1 = cnt[t2 + 1];
    int s1 = v0 + v1;
    int lane = tid & 31, wid = tid >> 5;
    int x = s1;
#pragma unroll
    for (int o = 1; o < 32; o <<= 1) {
        int y = __shfl_up_sync(0xffffffffu, x, o);
        if (lane >= o) x += y;
    }
    if (lane == 31) wsum[wid] = x;
    __syncthreads();
    if (tid == 0) {
        int a = 0;
        for (int w = 0; w < 16; w++) { int tt = wsum[w]; wsum[w] = a; a += tt; }
    }
    __syncthreads();
    int e = wsum[wid] + x - s1;
    start[t2] = e;
    start[t2 + 1] = e + v0;
}

// ---------------------------------------------------------------------------
// Stage 1 (R13 proven): one block (512 thr) per glimpse. CSR over cluster1 in
// smem, owner-computes: ps1 mean, msg1 (4->16) relu+max, f1 = celu(.@W1g).
// ---------------------------------------------------------------------------
__global__ void __launch_bounds__(512) k_stage1(
    const float* __restrict__ rgb, const float* __restrict__ pos,
    const int* __restrict__ cl1, const float* __restrict__ Wp1l,
    const float* __restrict__ b1l, const float* __restrict__ Wp1g,
    const float* __restrict__ b1g, float* __restrict__ ps1, float* __restrict__ f1,
    int* __restrict__ glo1, int P, int G) {
    __shared__ __align__(16) float4 pts[1024];
    __shared__ int cls[1024];
    __shared__ int cnt[1024];
    __shared__ int start[1024];
    __shared__ int fill[1024];
    __shared__ int csr[1024];
    __shared__ __align__(16) float wl[64];
    __shared__ __align__(16) float wg[512];
    __shared__ float blv[16], bgv[32];
    __shared__ int wsum[16];
    __shared__ int s_lo, s_hi;
    int tid = threadIdx.x, g = blockIdx.x;
    if (tid == 0) { s_lo = 0x7fffffff; s_hi = -1; }
    if (tid < 64) wl[tid] = Wp1l[tid];
    wg[tid] = Wp1g[tid];
    if (tid < 16) blv[tid] = b1l[tid];
    if (tid < 32) bgv[tid] = b1g[tid];
    for (int t = tid; t < 1024; t += 512) { cnt[t] = 0; fill[t] = 0; }
    __syncthreads();
    int lmin = 0x7fffffff, lmax = -1;
    for (int i = tid; i < P; i += 512) {
        int gi = g * P + i;
        pts[i] = make_float4(pos[3 * gi], pos[3 * gi + 1], pos[3 * gi + 2], rgb[gi]);
        int c = cl1[gi];
        cls[i] = c;
        lmin = min(lmin, c);
        lmax = max(lmax, c);
    }
    atomicMin(&s_lo, lmin);
    atomicMax(&s_hi, lmax);
    __syncthreads();
    int lo = s_lo, W = s_hi - lo + 1;
    for (int i = tid; i < P; i += 512) {
        int l = cls[i] - lo;
        cls[i] = l;
        atomicAdd(&cnt[l], 1);
    }
    __syncthreads();
    scan1024_512(cnt, start, wsum, tid);
    __syncthreads();
    for (int i = tid; i < P; i += 512) {
        int l = cls[i];
        csr[start[l] + atomicAdd(&fill[l], 1)] = i;
    }
    __syncthreads();
    for (int v = tid; v < W; v += 512) {
        int s = start[v], c = cnt[v];
        float sx = 0.f, sy = 0.f, sz = 0.f;
        for (int q = 0; q < c; q++) {
            float4 p = pts[csr[s + q]];
            sx += p.x; sy += p.y; sz += p.z;
        }
        float inv = 1.0f / (float)c;
        float mx = sx * inv, my = sy * inv, mz = sz * inv;
        int vg = lo + v;
        ps1[3 * vg] = mx; ps1[3 * vg + 1] = my; ps1[3 * vg + 2] = mz;
        float m[16];
#pragma unroll
        for (int j = 0; j < 16; j++) m[j] = 0.f;
        for (int q = 0; q < c; q++) {
            float4 p = pts[csr[s + q]];
            ull p0 = pk2(p.w, p.x - mx);
            ull p1 = pk2(p.y - my, p.z - mz);
#pragma unroll
            for (int j = 0; j < 16; j++) {
                ull acc = 0ull;
                ffma2(acc, p0, ld2(&wl[2 * j]));
                ffma2(acc, p1, ld2(&wl[32 + 2 * j]));
                float r = ull_sum(acc) + blv[j];
                m[j] = fmaxf(m[j], fmaxf(r, 0.f));
            }
        }
        ull mp[8];
#pragma unroll
        for (int k2 = 0; k2 < 8; k2++) mp[k2] = pk2(m[2 * k2], m[2 * k2 + 1]);
        float* f1row = f1 + (size_t)vg * 32;
#pragma unroll
        for (int jo = 0; jo < 32; jo += 4) {
            float4 o4;
            float* po = (float*)&o4;
#pragma unroll
            for (int u = 0; u < 4; u++) {
                int j = jo + u;
                ull acc = 0ull;
#pragma unroll
                for (int k2 = 0; k2 < 8; k2++) ffma2(acc, mp[k2], ld2(&wg[k2 * 64 + 2 * j]));
                po[u] = celu1(ull_sum(acc) + bgv[j]);
            }
            *(float4*)(f1row + jo) = o4;
        }
    }
    if (tid == 0) {
        glo1[g] = lo;
        if (g == G - 1) glo1[G] = lo + W;
    }
}

// ---------------------------------------------------------------------------
// Stage 2 (R13 proven + 2-CTA bound + float4 weight preload): one block
// (512 thr / 16 warps) per glimpse. CSR over cluster2; per-warp owner-computes
// msg2 (35->64, 4-edge batches, FLOAT4 staging) relu+max, then f2 = celu(.@W2g).
// ---------------------------------------------------------------------------
#define SMB_INTS (5 * 1024 + 64 + 16 + 2)
#define SMB_FLOATS (2304 + 8192 + 64 + 128 + 3072 + 16 * 144 + 16 * 256)
#define SMB_BYTES ((SMB_FLOATS + SMB_INTS) * 4)
__global__ void __launch_bounds__(512, 2) k_stage2(
    const float* __restrict__ ps1, const float* __restrict__ f1,
    const int* __restrict__ cl2, const int* __restrict__ glo1,
    const float* __restrict__ Wp2l, const float* __restrict__ b2l,
    const float* __restrict__ Wp2g, const float* __restrict__ b2g,
    float* __restrict__ ps2, float* __restrict__ f2, int* __restrict__ glo2, int G) {
    extern __shared__ float sm[];
    float* Wl = sm;                     // 2304
    float* Wg = Wl + 2304;              // 8192
    float* bl = Wg + 8192;              // 64
    float* bg = bl + 64;                // 128
    float* ps2loc = bg + 128;           // 3072
    float* ins = ps2loc + 3072;         // 16*144
    float* aggs = ins + 16 * 144;       // 16*256
    int* cls = (int*)(aggs + 16 * 256); // 1024
    int* cnt = cls + 1024;
    int* start = cnt + 1024;
    int* fill = start + 1024;
    int* csr = fill + 1024;
    int* vpend = csr + 1024;            // 64
    int* wsum = vpend + 64;             // 16
    int* s_lohi = wsum + 16;            // 2
    int tid = threadIdx.x, g = blockIdx.x;
    int lane = tid & 31, wid = tid >> 5;
    for (int t = tid; t < 576; t += 512)
        *(float4*)&Wl[4 * t] = *(const float4*)&Wp2l[4 * t];
    for (int t = tid; t < 2048; t += 512)
        *(float4*)&Wg[4 * t] = *(const float4*)&Wp2g[4 * t];
    if (tid < 64) bl[tid] = b2l[tid];
    if (tid < 128) bg[tid] = b2g[tid];
    if (tid == 0) { s_lohi[0] = 0x7fffffff; s_lohi[1] = -1; }
    for (int t = tid; t < 1024; t += 512) { cnt[t] = 0; fill[t] = 0; }
    __syncthreads();
    int L = glo1[g], W1 = glo1[g + 1] - L;
    int lmin = 0x7fffffff, lmax = -1;
    for (int i = tid; i < W1; i += 512) {
        int c = cl2[L + i];
        cls[i] = c;
        lmin = min(lmin, c);
        lmax = max(lmax, c);
    }
    atomicMin(&s_lohi[0], lmin);
    atomicMax(&s_lohi[1], lmax);
    __syncthreads();
    int lo2 = s_lohi[0], W2 = s_lohi[1] - lo2 + 1;
    for (int i = tid; i < W1; i += 512) {
        int l = cls[i] - lo2;
        cls[i] = l;
        atomicAdd(&cnt[l], 1);
    }
    __syncthreads();
    scan1024_512(cnt, start, wsum, tid);
    __syncthreads();
    for (int i = tid; i < W1; i += 512) {
        int l = cls[i];
        csr[start[l] + atomicAdd(&fill[l], 1)] = i;
    }
    __syncthreads();
    for (int v = tid; v < W2; v += 512) {
        int s = start[v], c = cnt[v];
        float sx = 0.f, sy = 0.f, sz = 0.f;
        for (int q = 0; q < c; q++) {
            int e = L + csr[s + q];
            sx += ps1[3 * e]; sy += ps1[3 * e + 1]; sz += ps1[3 * e + 2];
        }
        float inv = 1.0f / (float)c;
        sx *= inv; sy *= inv; sz *= inv;
        ps2loc[3 * v] = sx; ps2loc[3 * v + 1] = sy; ps2loc[3 * v + 2] = sz;
        int vg = lo2 + v;
        ps2[3 * vg] = sx; ps2[3 * vg + 1] = sy; ps2[3 * vg + 2] = sz;
    }
    __syncthreads();
    float* insW = ins + wid * 144;
    float* aggW = aggs + wid * 256;
    int* vpW = vpend + wid * 4;
    int npend = 0;
    int se = lane >> 3, sq = lane & 7;
    int re = lane >> 2, rk = lane & 3;
    for (int v = wid; v < W2; v += 16) {
        int s = start[v], c = cnt[v];
        float m0 = 0.f, m1 = 0.f;
        for (int base = 0; base < c; base += 4) {
            __syncwarp();
            {
                int ee = base + se;
                if (ee >= c) ee = c - 1;
                int eg = L + csr[s + ee];
                *(float4*)&insW[se * 36 + 4 * sq] =
                    *(const float4*)&f1[(size_t)eg * 32 + 4 * sq];
                if (lane < 16) {
                    int ee2 = base + re;
                    if (ee2 >= c) ee2 = c - 1;
                    int eg2 = L + csr[s + ee2];
                    float val = 0.f;
                    if (rk < 3) val = ps1[3 * eg2 + rk] - ps2loc[3 * v + rk];
                    insW[re * 36 + 32 + rk] = val;
                }
            }
            __syncwarp();
            ull a00 = 0, a01 = 0, a02 = 0, a03 = 0, a10 = 0, a11 = 0, a12 = 0, a13 = 0;
#pragma unroll
            for (int k2 = 0; k2 < 18; k2++) {
                ull w0 = ld2(&Wl[k2 * 128 + 2 * lane]);
                ull w1 = ld2(&Wl[k2 * 128 + 64 + 2 * lane]);
                ull x0 = ld2(&insW[0 * 36 + 2 * k2]);
                ull x1 = ld2(&insW[1 * 36 + 2 * k2]);
                ull x2 = ld2(&insW[2 * 36 + 2 * k2]);
                ull x3 = ld2(&insW[3 * 36 + 2 * k2]);
                ffma2(a00, x0, w0); ffma2(a01, x1, w0); ffma2(a02, x2, w0); ffma2(a03, x3, w0);
                ffma2(a10, x0, w1); ffma2(a11, x1, w1); ffma2(a12, x2, w1); ffma2(a13, x3, w1);
            }
            float b0 = bl[lane], b1 = bl[lane + 32];
            m0 = fmaxf(m0, fmaxf(ull_sum(a00) + b0, 0.f));
            m0 = fmaxf(m0, fmaxf(ull_sum(a01) + b0, 0.f));
            m0 = fmaxf(m0, fmaxf(ull_sum(a02) + b0, 0.f));
            m0 = fmaxf(m0, fmaxf(ull_sum(a03) + b0, 0.f));
            m1 = fmaxf(m1, fmaxf(ull_sum(a10) + b1, 0.f));
            m1 = fmaxf(m1, fmaxf(ull_sum(a11) + b1, 0.f));
            m1 = fmaxf(m1, fmaxf(ull_sum(a12) + b1, 0.f));
            m1 = fmaxf(m1, fmaxf(ull_sum(a13) + b1, 0.f));
        }
        __syncwarp();
        aggW[npend * 64 + lane] = m0;
        aggW[npend * 64 + 32 + lane] = m1;
        vpW[npend] = lo2 + v;
        npend++;
        if (npend == 4) {
            __syncwarp();
#pragma unroll
            for (int u = 0; u < 4; u++) {
                int j = lane + 32 * u;
                ull acc0 = 0, acc1 = 0, acc2 = 0, acc3 = 0;
#pragma unroll 8
                for (int k2 = 0; k2 < 32; k2++) {
                    ull w = ld2(&Wg[k2 * 256 + 2 * j]);
                    ffma2(acc0, ld2(&aggW[0 * 64 + 2 * k2]), w);
                    ffma2(acc1, ld2(&aggW[1 * 64 + 2 * k2]), w);
                    ffma2(acc2, ld2(&aggW[2 * 64 + 2 * k2]), w);
                    ffma2(acc3, ld2(&aggW[3 * 64 + 2 * k2]), w);
                }
                float bb = bg[j];
                f2[(size_t)vpW[0] * 128 + j] = celu1(ull_sum(acc0) + bb);
                f2[(size_t)vpW[1] * 128 + j] = celu1(ull_sum(acc1) + bb);
                f2[(size_t)vpW[2] * 128 + j] = celu1(ull_sum(acc2) + bb);
                f2[(size_t)vpW[3] * 128 + j] = celu1(ull_sum(acc3) + bb);
            }
            __syncwarp();
            npend = 0;
        }
    }
    if (npend) {
        __syncwarp();
#pragma unroll
        for (int u = 0; u < 4; u++) {
            int j = lane + 32 * u;
            ull acc0 = 0, acc1 = 0, acc2 = 0;
#pragma unroll 8
            for (int k2 = 0; k2 < 32; k2++) {
                ull w = ld2(&Wg[k2 * 256 + 2 * j]);
                ffma2(acc0, ld2(&aggW[0 * 64 + 2 * k2]), w);
                ffma2(acc1, ld2(&aggW[1 * 64 + 2 * k2]), w);
                ffma2(acc2, ld2(&aggW[2 * 64 + 2 * k2]), w);
            }
            float bb = bg[j];
            if (npend > 0) f2[(size_t)vpW[0] * 128 + j] = celu1(ull_sum(acc0) + bb);
            if (npend > 1) f2[(size_t)vpW[1] * 128 + j] = celu1(ull_sum(acc1) + bb);
            if (npend > 2) f2[(size_t)vpW[2] * 128 + j] = celu1(ull_sum(acc2) + bb);
        }
    }
    if (tid == 0) {
        glo2[g] = lo2;
        if (g == G - 1) glo2[G] = lo2 + W2;
    }
}

// ---------------------------------------------------------------------------
// msg3 v3 (PROVEN, FINAL): persistent grid-stride, 128-edge tiles, 512 thr,
// plain staging. k-paired reduction, 8 consecutive edges x 4 j.
// ---------------------------------------------------------------------------
#define MSG3_ROW 136
#define SM_MSG3_FLOATS (16896 + 128 * MSG3_ROW + 128)
#define SM_MSG3_BYTES (SM_MSG3_FLOATS * 4 + 128 * 4)
__global__ void __launch_bounds__(512) k_msg3(
    const float* __restrict__ f2, const float* __restrict__ ps2,
    const int* __restrict__ bt2, const float* __restrict__ Wp3l,
    const float* __restrict__ b3l, float* __restrict__ agg3, int n) {
    extern __shared__ float sm[];
    float* Wsm = sm;                         // 66*256 = 16896 (k-paired)
    float* ins = Wsm + 16896;                // 128*136
    float* bsm = ins + 128 * MSG3_ROW;       // 128
    int* slots = (int*)(bsm + 128);          // 128
    int tid = threadIdx.x;
    int lane = tid & 31, eg = tid >> 5;      // eg 0..15: edges eg*8..eg*8+7
    for (int t = tid; t < 4224; t += 512)
        *(float4*)&Wsm[4 * t] = *(const float4*)&Wp3l[4 * t];
    if (tid < 128) bsm[tid] = b3l[tid];
    int ntiles = (n + 127) >> 7;
    for (int tile = blockIdx.x; tile < ntiles; tile += gridDim.x) {
        int base = tile << 7;
        __syncthreads();
        for (int idx = tid; idx < 128 * 32; idx += 512) {
            int e = idx >> 5, q = idx & 31;
            int i = base + e;
            if (i >= n) i = n - 1;
            *(float4*)&ins[e * MSG3_ROW + 4 * q] = *(const float4*)&f2[(size_t)i * 128 + 4 * q];
        }
        if (tid < 128) {
            int e = tid;
            int i = base + e;
            if (i >= n) i = n - 1;
            ins[e * MSG3_ROW + 128] = ps2[3 * i];
            ins[e * MSG3_ROW + 129] = ps2[3 * i + 1];
            ins[e * MSG3_ROW + 130] = ps2[3 * i + 2];
            ins[e * MSG3_ROW + 131] = 0.f;
            slots[e] = bt2[i];
        }
        __syncthreads();
        const float* insE = ins + eg * 8 * MSG3_ROW;
        ull acc[8][4];
#pragma unroll
        for (int i = 0; i < 8; i++)
#pragma unroll
            for (int u = 0; u < 4; u++) acc[i][u] = 0ull;
#pragma unroll 2
        for (int k2 = 0; k2 < 66; k2++) {
            ull x[8];
#pragma unroll
            for (int i = 0; i < 8; i++) x[i] = ld2(&insE[i * MSG3_ROW + 2 * k2]);
            const float* wr = &Wsm[k2 * 256 + 2 * lane];
#pragma unroll
            for (int u = 0; u < 4; u++) {
                ull w = ld2(wr + 64 * u);
#pragma unroll
                for (int i = 0; i < 8; i++) ffma2(acc[i][u], x[i], w);
            }
        }
        int gs[8];
#pragma unroll
        for (int i = 0; i < 8; i++) gs[i] = slots[eg * 8 + i];
#pragma unroll
        for (int u = 0; u < 4; u++) {
            int j = lane + 32 * u;
            float bb = bsm[j];
            float v[8];
#pragma unroll
            for (int i = 0; i < 8; i++) v[i] = fmaxf(ull_sum(acc[i][u]) + bb, 0.f);
            int i = 0;
            while (i < 8) {
                int g = gs[i];
                float mv = v[i];
                int f = i + 1;
                while (f < 8 && gs[f] == g) { mv = fmaxf(mv, v[f]); f++; }
                atomicMax((unsigned int*)&agg3[(size_t)g * 128 + j], __float_as_uint(mv));
                i = f;
            }
        }
    }
}

// ------------- fused f3 + head: 8 glimpses/block, 256 threads ---------------
__global__ void __launch_bounds__(256) k_f3head(
    const float* __restrict__ agg3, const float* __restrict__ Wp3g,
    const float* __restrict__ b3g, const float* __restrict__ Wplin,
    const float* __restrict__ blin, const float* __restrict__ eps,
    float* __restrict__ f3, float* __restrict__ out, int G) {
    __shared__ __align__(16) float a3[8 * 128];
    __shared__ __align__(16) float fs[8 * 256];
    __shared__ float sig_s[8 * 128];
    int tid = threadIdx.x;
    int g0 = blockIdx.x * 8;
    {
        int e = tid >> 5, kq = tid & 31;
        int g = g0 + e;
        float4 v = make_float4(0.f, 0.f, 0.f, 0.f);
        if (g < G) v = *(const float4*)&agg3[(size_t)g * 128 + 4 * kq];
        *(float4*)&a3[e * 128 + 4 * kq] = v;
    }
    __syncthreads();
    {
        ull acc[8];
#pragma unroll
        for (int e = 0; e < 8; e++) acc[e] = 0ull;
#pragma unroll 4
        for (int k2 = 0; k2 < 64; k2++) {
            ull w = ld2(&Wp3g[k2 * 512 + 2 * tid]);
#pragma unroll
            for (int e = 0; e < 8; e++) ffma2(acc[e], ld2(&a3[e * 128 + 2 * k2]), w);
        }
        float bb = __ldg(&b3g[tid]);
#pragma unroll
        for (int e = 0; e < 8; e++) {
            int g = g0 + e;
            float vv = celu1(ull_sum(acc[e]) + bb);
            fs[e * 256 + tid] = vv;
            if (g < G) f3[(size_t)g * 256 + tid] = vv;
        }
    }
    __syncthreads();
    ull acc[8];
#pragma unroll
    for (int e = 0; e < 8; e++) acc[e] = 0ull;
#pragma unroll 4
    for (int k2 = 0; k2 < 128; k2++) {
        ull w = ld2(&Wplin[k2 * 512 + 2 * tid]);
#pragma unroll
        for (int e = 0; e < 8; e++) ffma2(acc[e], ld2(&fs[e * 256 + 2 * k2]), w);
    }
    float bb = __ldg(&blin[tid]);
    float val[8];
#pragma unroll
    for (int e = 0; e < 8; e++) val[e] = ull_sum(acc[e]) + bb;
    if (tid >= 128) {
        int j = tid - 128;
#pragma unroll
        for (int e = 0; e < 8; e++) {
            float s = val[e];
            float sg = fmaxf(s, 0.0f) + log1pf(expf(-fabsf(s)));
            sig_s[e * 128 + j] = sg;
            int g = g0 + e;
            if (g < G) out[(size_t)G * 256 + (size_t)g * 128 + j] = sg;
        }
    }
    __syncthreads();
    if (tid < 128) {
        int j = tid;
#pragma unroll
        for (int e = 0; e < 8; e++) {
            int g = g0 + e;
            if (g >= G) continue;
            float mu = val[e];
            float sg = sig_s[e * 128 + j];
            float z = fmaf(sg, eps[(size_t)g * 128 + j], mu);
            out[(size_t)G * 128 + (size_t)g * 128 + j] = mu;
            if (j < 64) out[(size_t)g * 64 + j] = z;
            else out[(size_t)G * 64 + (size_t)g * 64 + (j - 64)] = z;
        }
    }
}

// ---------------------------------------------------------------------------
extern "C" void kernel_launch(void* const* d_in, const int* in_sizes, int n_in,
                              void* d_out, int out_size) {
    const float* rgb = (const float*)d_in[0];
    const float* pos = (const float*)d_in[1];
    const float* W1l = (const float*)d_in[3];
    const float* b1l = (const float*)d_in[4];
    const float* W1g = (const float*)d_in[5];
    const float* b1g = (const float*)d_in[6];
    const float* W2l = (const float*)d_in[7];
    const float* b2l = (const float*)d_in[8];
    const float* W2g = (const float*)d_in[9];
    const float* b2g = (const float*)d_in[10];
    const float* W3l = (const float*)d_in[11];
    const float* b3l = (const float*)d_in[12];
    const float* W3g = (const float*)d_in[13];
    const float* b3g = (const float*)d_in[14];
    const float* Wlin = (const float*)d_in[15];
    const float* blin = (const float*)d_in[16];
    const float* eps = (const float*)d_in[17];
    const int* cl1 = (const int*)d_in[19];
    const int* cl2 = (const int*)d_in[20];
    const int* bt2 = (const int*)d_in[21];

    int N = in_sizes[0];
    int G = in_sizes[2] / 3;
    int M1 = in_sizes[20];
    int M2 = in_sizes[21];
    int P = N / G;

    float* A = nullptr;
    cudaGetSymbolAddress((void**)&A, g_arena);
    size_t o = 0;
    float* f1 = A + o;   o += 32ull * M1;       o = (o + 31) & ~31ull;
    float* ps1 = A + o;  o += 3ull * M1;        o = (o + 31) & ~31ull;
    float* ps2 = A + o;  o += 3ull * M2;        o = (o + 31) & ~31ull;
    float* f2 = A + o;   o += 128ull * M2;      o = (o + 31) & ~31ull;
    float* agg3 = A + o; o += 128ull * G;       o = (o + 31) & ~31ull;
    int* glo1 = (int*)(A + o); o += (size_t)G + 32; o = (o + 31) & ~31ull;
    int* glo2 = (int*)(A + o); o += (size_t)G + 32; o = (o + 31) & ~31ull;
    float* Wp1l = A + o;  o += 64;
    float* Wp1g = A + o;  o += 512;
    float* Wp2l = A + o;  o += 2304;
    float* Wp2g = A + o;  o += 8192;
    float* Wp3g = A + o;  o += 32768;
    float* Wplin = A + o; o += 65536;
    float* Wp3l = A + o;  o += 16896;

    float* out = (float*)d_out;
    float* f3 = out + (size_t)G * 384;

    k_prep<<<(126272 + 32 * G + 255) / 256, 256>>>(W1l, W1g, W2l, W2g, W3g, Wlin, W3l,
                                                   Wp1l, Wp1g, Wp2l, Wp2g, Wp3g,
                                                   Wplin, Wp3l, agg3, G);

    k_stage1<<<G, 512>>>(rgb, pos, cl1, Wp1l, b1l, Wp1g, b1g, ps1, f1, glo1, P, G);

    cudaFuncSetAttribute(k_stage2, cudaFuncAttributeMaxDynamicSharedMemorySize, SMB_BYTES);
    k_stage2<<<G, 512, SMB_BYTES>>>(ps1, f1, cl2, glo1, Wp2l, b2l, Wp2g, b2g,
                                    ps2, f2, glo2, G);

    cudaFuncSetAttribute(k_msg3, cudaFuncAttributeMaxDynamicSharedMemorySize,
                         SM_MSG3_BYTES);
    k_msg3<<<148, 512, SM_MSG3_BYTES>>>(f2, ps2, bt2, Wp3l, b3l, agg3, M2);

    k_f3head<<<(G + 7) / 8, 256>>>(agg3, Wp3g, b3g, Wplin, blin, eps, f3, out, G);
}

// round 16
// speedup vs baseline: 1.0208x; 1.0029x over previous
#include <cuda_runtime.h>
#include <math.h>

typedef unsigned long long ull;

// ---------------------------------------------------------------------------
// Arena: f1(32M1) ps1(3M1) ps2(3M2) f2(128M2) agg3(128G) glo1/glo2 packs
#define MAXN (1u << 20)
static __device__ float g_arena[167ull * MAXN + 262144ull];

__device__ __forceinline__ float celu1(float x) { return x > 0.f ? x : expm1f(x); }
__device__ __forceinline__ void ffma2(ull& d, ull a, ull b) {
    asm("fma.rn.f32x2 %0, %1, %2, %0;" : "+l"(d) : "l"(a), "l"(b));
}
__device__ __forceinline__ float ull_sum(ull v) {
    float a, b;
    asm("mov.b64 {%0, %1}, %2;" : "=f"(a), "=f"(b) : "l"(v));
    return a + b;
}
__device__ __forceinline__ ull ld2(const float* p) { return *(const ull*)p; }
__device__ __forceinline__ ull pk2(float a, float b) {
    ull r;
    asm("mov.b64 %0, {%1, %2};" : "=l"(r) : "f"(a), "f"(b));
    return r;
}

// ------------------- weight pre-pack: k-paired interleave -------------------
__device__ __forceinline__ void packw(float* dst, const float* src, int K, int C, int t) {
    int k2 = t / (2 * C);
    int col = t - k2 * 2 * C;
    int j = col >> 1;
    int k = 2 * k2 + (col & 1);
    dst[t] = (k < K) ? src[k * C + j] : 0.0f;
}
// packs total 126272 floats; then zero agg3 (128G floats) via float4
__global__ void k_prep(const float* __restrict__ W1l, const float* __restrict__ W1g,
                       const float* __restrict__ W2l, const float* __restrict__ W2g,
                       const float* __restrict__ W3g, const float* __restrict__ Wlin,
                       const float* __restrict__ W3l,
                       float* Wp1l, float* Wp1g, float* Wp2l, float* Wp2g,
                       float* Wp3g, float* Wplin, float* Wp3l,
                       float* agg3, int G) {
    int t = blockIdx.x * blockDim.x + threadIdx.x;
    if (t < 64) packw(Wp1l, W1l, 4, 16, t);
    else if (t < 576) packw(Wp1g, W1g, 16, 32, t - 64);
    else if (t < 2880) packw(Wp2l, W2l, 35, 64, t - 576);
    else if (t < 11072) packw(Wp2g, W2g, 64, 128, t - 2880);
    else if (t < 43840) packw(Wp3g, W3g, 128, 256, t - 11072);
    else if (t < 109376) packw(Wplin, Wlin, 256, 256, t - 43840);
    else if (t < 126272) packw(Wp3l, W3l, 131, 128, t - 109376);
    else {
        int z = t - 126272;
        if (z < 32 * G)
            *(float4*)&agg3[4 * z] = make_float4(0.f, 0.f, 0.f, 0.f);
    }
}

// --------- block-wide exclusive scan of 1024 ints with 512 threads ----------
__device__ __forceinline__ void scan1024_512(const int* cnt, int* start, int* wsum,
                                             int tid) {
    int t2 = tid * 2;
    int v0 = cnt[t2], v1 = cnt[t2 + 1];
    int s1 = v0 + v1;
    int lane = tid & 31, wid = tid >> 5;
    int x = s1;
#pragma unroll
    for (int o = 1; o < 32; o <<= 1) {
        int y = __shfl_up_sync(0xffffffffu, x, o);
        if (lane >= o) x += y;
    }
    if (lane == 31) wsum[wid] = x;
    __syncthreads();
    if (tid == 0) {
        int a = 0;
        for (int w = 0; w < 16; w++) { int tt = wsum[w]; wsum[w] = a; a += tt; }
    }
    __syncthreads();
    int e = wsum[wid] + x - s1;
    start[t2] = e;
    start[t2 + 1] = e + v0;
}

// ---------------------------------------------------------------------------
// Stage 1 (R13 proven): one block (512 thr) per glimpse. CSR over cluster1 in
// smem, owner-computes: ps1 mean, msg1 (4->16) relu+max, f1 = celu(.@W1g).
// ---------------------------------------------------------------------------
__global__ void __launch_bounds__(512) k_stage1(
    const float* __restrict__ rgb, const float* __restrict__ pos,
    const int* __restrict__ cl1, const float* __restrict__ Wp1l,
    const float* __restrict__ b1l, const float* __restrict__ Wp1g,
    const float* __restrict__ b1g, float* __restrict__ ps1, float* __restrict__ f1,
    int* __restrict__ glo1, int P, int G) {
    __shared__ __align__(16) float4 pts[1024];
    __shared__ int cls[1024];
    __shared__ int cnt[1024];
    __shared__ int start[1024];
    __shared__ int fill[1024];
    __shared__ int csr[1024];
    __shared__ __align__(16) float wl[64];
    __shared__ __align__(16) float wg[512];
    __shared__ float blv[16], bgv[32];
    __shared__ int wsum[16];
    __shared__ int s_lo, s_hi;
    int tid = threadIdx.x, g = blockIdx.x;
    if (tid == 0) { s_lo = 0x7fffffff; s_hi = -1; }
    if (tid < 64) wl[tid] = Wp1l[tid];
    wg[tid] = Wp1g[tid];
    if (tid < 16) blv[tid] = b1l[tid];
    if (tid < 32) bgv[tid] = b1g[tid];
    for (int t = tid; t < 1024; t += 512) { cnt[t] = 0; fill[t] = 0; }
    __syncthreads();
    int lmin = 0x7fffffff, lmax = -1;
    for (int i = tid; i < P; i += 512) {
        int gi = g * P + i;
        pts[i] = make_float4(pos[3 * gi], pos[3 * gi + 1], pos[3 * gi + 2], rgb[gi]);
        int c = cl1[gi];
        cls[i] = c;
        lmin = min(lmin, c);
        lmax = max(lmax, c);
    }
    atomicMin(&s_lo, lmin);
    atomicMax(&s_hi, lmax);
    __syncthreads();
    int lo = s_lo, W = s_hi - lo + 1;
    for (int i = tid; i < P; i += 512) {
        int l = cls[i] - lo;
        cls[i] = l;
        atomicAdd(&cnt[l], 1);
    }
    __syncthreads();
    scan1024_512(cnt, start, wsum, tid);
    __syncthreads();
    for (int i = tid; i < P; i += 512) {
        int l = cls[i];
        csr[start[l] + atomicAdd(&fill[l], 1)] = i;
    }
    __syncthreads();
    for (int v = tid; v < W; v += 512) {
        int s = start[v], c = cnt[v];
        float sx = 0.f, sy = 0.f, sz = 0.f;
        for (int q = 0; q < c; q++) {
            float4 p = pts[csr[s + q]];
            sx += p.x; sy += p.y; sz += p.z;
        }
        float inv = 1.0f / (float)c;
        float mx = sx * inv, my = sy * inv, mz = sz * inv;
        int vg = lo + v;
        ps1[3 * vg] = mx; ps1[3 * vg + 1] = my; ps1[3 * vg + 2] = mz;
        float m[16];
#pragma unroll
        for (int j = 0; j < 16; j++) m[j] = 0.f;
        for (int q = 0; q < c; q++) {
            float4 p = pts[csr[s + q]];
            ull p0 = pk2(p.w, p.x - mx);
            ull p1 = pk2(p.y - my, p.z - mz);
#pragma unroll
            for (int j = 0; j < 16; j++) {
                ull acc = 0ull;
                ffma2(acc, p0, ld2(&wl[2 * j]));
                ffma2(acc, p1, ld2(&wl[32 + 2 * j]));
                float r = ull_sum(acc) + blv[j];
                m[j] = fmaxf(m[j], fmaxf(r, 0.f));
            }
        }
        ull mp[8];
#pragma unroll
        for (int k2 = 0; k2 < 8; k2++) mp[k2] = pk2(m[2 * k2], m[2 * k2 + 1]);
        float* f1row = f1 + (size_t)vg * 32;
#pragma unroll
        for (int jo = 0; jo < 32; jo += 4) {
            float4 o4;
            float* po = (float*)&o4;
#pragma unroll
            for (int u = 0; u < 4; u++) {
                int j = jo + u;
                ull acc = 0ull;
#pragma unroll
                for (int k2 = 0; k2 < 8; k2++) ffma2(acc, mp[k2], ld2(&wg[k2 * 64 + 2 * j]));
                po[u] = celu1(ull_sum(acc) + bgv[j]);
            }
            *(float4*)(f1row + jo) = o4;
        }
    }
    if (tid == 0) {
        glo1[g] = lo;
        if (g == G - 1) glo1[G] = lo + W;
    }
}

// ---------------------------------------------------------------------------
// Stage 2 PERSISTENT: 296 blocks (512 thr / 16 warps) grid-striding over
// glimpses; weights loaded ONCE per block. Per-glimpse body identical to the
// proven R15 kernel: CSR over cluster2; per-warp owner-computes msg2 (35->64,
// 4-edge batches, float4 staging) relu+max, then f2 = celu(.@W2g).
// ---------------------------------------------------------------------------
#define SMB_INTS (5 * 1024 + 64 + 16 + 2)
#define SMB_FLOATS (2304 + 8192 + 64 + 128 + 3072 + 16 * 144 + 16 * 256)
#define SMB_BYTES ((SMB_FLOATS + SMB_INTS) * 4)
__global__ void __launch_bounds__(512, 2) k_stage2(
    const float* __restrict__ ps1, const float* __restrict__ f1,
    const int* __restrict__ cl2, const int* __restrict__ glo1,
    const float* __restrict__ Wp2l, const float* __restrict__ b2l,
    const float* __restrict__ Wp2g, const float* __restrict__ b2g,
    float* __restrict__ ps2, float* __restrict__ f2, int* __restrict__ glo2, int G) {
    extern __shared__ float sm[];
    float* Wl = sm;                     // 2304
    float* Wg = Wl + 2304;              // 8192
    float* bl = Wg + 8192;              // 64
    float* bg = bl + 64;                // 128
    float* ps2loc = bg + 128;           // 3072
    float* ins = ps2loc + 3072;         // 16*144
    float* aggs = ins + 16 * 144;       // 16*256
    int* cls = (int*)(aggs + 16 * 256); // 1024
    int* cnt = cls + 1024;
    int* start = cnt + 1024;
    int* fill = start + 1024;
    int* csr = fill + 1024;
    int* vpend = csr + 1024;            // 64
    int* wsum = vpend + 64;             // 16
    int* s_lohi = wsum + 16;            // 2
    int tid = threadIdx.x;
    int lane = tid & 31, wid = tid >> 5;
    // weights/bias once per block
    for (int t = tid; t < 576; t += 512)
        *(float4*)&Wl[4 * t] = *(const float4*)&Wp2l[4 * t];
    for (int t = tid; t < 2048; t += 512)
        *(float4*)&Wg[4 * t] = *(const float4*)&Wp2g[4 * t];
    if (tid < 64) bl[tid] = b2l[tid];
    if (tid < 128) bg[tid] = b2g[tid];
    int se = lane >> 3, sq = lane & 7;
    int re = lane >> 2, rk = lane & 3;

    for (int g = blockIdx.x; g < G; g += gridDim.x) {
        __syncthreads();  // smem reuse guard (covers weight load on first iter)
        if (tid == 0) { s_lohi[0] = 0x7fffffff; s_lohi[1] = -1; }
        for (int t = tid; t < 1024; t += 512) { cnt[t] = 0; fill[t] = 0; }
        __syncthreads();
        int L = glo1[g], W1 = glo1[g + 1] - L;
        int lmin = 0x7fffffff, lmax = -1;
        for (int i = tid; i < W1; i += 512) {
            int c = cl2[L + i];
            cls[i] = c;
            lmin = min(lmin, c);
            lmax = max(lmax, c);
        }
        atomicMin(&s_lohi[0], lmin);
        atomicMax(&s_lohi[1], lmax);
        __syncthreads();
        int lo2 = s_lohi[0], W2 = s_lohi[1] - lo2 + 1;
        for (int i = tid; i < W1; i += 512) {
            int l = cls[i] - lo2;
            cls[i] = l;
            atomicAdd(&cnt[l], 1);
        }
        __syncthreads();
        scan1024_512(cnt, start, wsum, tid);
        __syncthreads();
        for (int i = tid; i < W1; i += 512) {
            int l = cls[i];
            csr[start[l] + atomicAdd(&fill[l], 1)] = i;
        }
        __syncthreads();
        for (int v = tid; v < W2; v += 512) {
            int s = start[v], c = cnt[v];
            float sx = 0.f, sy = 0.f, sz = 0.f;
            for (int q = 0; q < c; q++) {
                int e = L + csr[s + q];
                sx += ps1[3 * e]; sy += ps1[3 * e + 1]; sz += ps1[3 * e + 2];
            }
            float inv = 1.0f / (float)c;
            sx *= inv; sy *= inv; sz *= inv;
            ps2loc[3 * v] = sx; ps2loc[3 * v + 1] = sy; ps2loc[3 * v + 2] = sz;
            int vg = lo2 + v;
            ps2[3 * vg] = sx; ps2[3 * vg + 1] = sy; ps2[3 * vg + 2] = sz;
        }
        __syncthreads();
        float* insW = ins + wid * 144;
        float* aggW = aggs + wid * 256;
        int* vpW = vpend + wid * 4;
        int npend = 0;
        for (int v = wid; v < W2; v += 16) {
            int s = start[v], c = cnt[v];
            float m0 = 0.f, m1 = 0.f;
            for (int base = 0; base < c; base += 4) {
                __syncwarp();
                {
                    int ee = base + se;
                    if (ee >= c) ee = c - 1;
                    int eg = L + csr[s + ee];
                    *(float4*)&insW[se * 36 + 4 * sq] =
                        *(const float4*)&f1[(size_t)eg * 32 + 4 * sq];
                    if (lane < 16) {
                        int ee2 = base + re;
                        if (ee2 >= c) ee2 = c - 1;
                        int eg2 = L + csr[s + ee2];
                        float val = 0.f;
                        if (rk < 3) val = ps1[3 * eg2 + rk] - ps2loc[3 * v + rk];
                        insW[re * 36 + 32 + rk] = val;
                    }
                }
                __syncwarp();
                ull a00 = 0, a01 = 0, a02 = 0, a03 = 0, a10 = 0, a11 = 0, a12 = 0, a13 = 0;
#pragma unroll
                for (int k2 = 0; k2 < 18; k2++) {
                    ull w0 = ld2(&Wl[k2 * 128 + 2 * lane]);
                    ull w1 = ld2(&Wl[k2 * 128 + 64 + 2 * lane]);
                    ull x0 = ld2(&insW[0 * 36 + 2 * k2]);
                    ull x1 = ld2(&insW[1 * 36 + 2 * k2]);
                    ull x2 = ld2(&insW[2 * 36 + 2 * k2]);
                    ull x3 = ld2(&insW[3 * 36 + 2 * k2]);
                    ffma2(a00, x0, w0); ffma2(a01, x1, w0); ffma2(a02, x2, w0); ffma2(a03, x3, w0);
                    ffma2(a10, x0, w1); ffma2(a11, x1, w1); ffma2(a12, x2, w1); ffma2(a13, x3, w1);
                }
                float b0 = bl[lane], b1 = bl[lane + 32];
                m0 = fmaxf(m0, fmaxf(ull_sum(a00) + b0, 0.f));
                m0 = fmaxf(m0, fmaxf(ull_sum(a01) + b0, 0.f));
                m0 = fmaxf(m0, fmaxf(ull_sum(a02) + b0, 0.f));
                m0 = fmaxf(m0, fmaxf(ull_sum(a03) + b0, 0.f));
                m1 = fmaxf(m1, fmaxf(ull_sum(a10) + b1, 0.f));
                m1 = fmaxf(m1, fmaxf(ull_sum(a11) + b1, 0.f));
                m1 = fmaxf(m1, fmaxf(ull_sum(a12) + b1, 0.f));
                m1 = fmaxf(m1, fmaxf(ull_sum(a13) + b1, 0.f));
            }
            __syncwarp();
            aggW[npend * 64 + lane] = m0;
            aggW[npend * 64 + 32 + lane] = m1;
            vpW[npend] = lo2 + v;
            npend++;
            if (npend == 4) {
                __syncwarp();
#pragma unroll
                for (int u = 0; u < 4; u++) {
                    int j = lane + 32 * u;
                    ull acc0 = 0, acc1 = 0, acc2 = 0, acc3 = 0;
#pragma unroll 8
                    for (int k2 = 0; k2 < 32; k2++) {
                        ull w = ld2(&Wg[k2 * 256 + 2 * j]);
                        ffma2(acc0, ld2(&aggW[0 * 64 + 2 * k2]), w);
                        ffma2(acc1, ld2(&aggW[1 * 64 + 2 * k2]), w);
                        ffma2(acc2, ld2(&aggW[2 * 64 + 2 * k2]), w);
                        ffma2(acc3, ld2(&aggW[3 * 64 + 2 * k2]), w);
                    }
                    float bb = bg[j];
                    f2[(size_t)vpW[0] * 128 + j] = celu1(ull_sum(acc0) + bb);
                    f2[(size_t)vpW[1] * 128 + j] = celu1(ull_sum(acc1) + bb);
                    f2[(size_t)vpW[2] * 128 + j] = celu1(ull_sum(acc2) + bb);
                    f2[(size_t)vpW[3] * 128 + j] = celu1(ull_sum(acc3) + bb);
                }
                __syncwarp();
                npend = 0;
            }
        }
        if (npend) {
            __syncwarp();
#pragma unroll
            for (int u = 0; u < 4; u++) {
                int j = lane + 32 * u;
                ull acc0 = 0, acc1 = 0, acc2 = 0;
#pragma unroll 8
                for (int k2 = 0; k2 < 32; k2++) {
                    ull w = ld2(&Wg[k2 * 256 + 2 * j]);
                    ffma2(acc0, ld2(&aggW[0 * 64 + 2 * k2]), w);
                    ffma2(acc1, ld2(&aggW[1 * 64 + 2 * k2]), w);
                    ffma2(acc2, ld2(&aggW[2 * 64 + 2 * k2]), w);
                }
                float bb = bg[j];
                if (npend > 0) f2[(size_t)vpW[0] * 128 + j] = celu1(ull_sum(acc0) + bb);
                if (npend > 1) f2[(size_t)vpW[1] * 128 + j] = celu1(ull_sum(acc1) + bb);
                if (npend > 2) f2[(size_t)vpW[2] * 128 + j] = celu1(ull_sum(acc2) + bb);
            }
        }
        if (tid == 0) {
            glo2[g] = lo2;
            if (g == G - 1) glo2[G] = lo2 + W2;
        }
    }
}

// ---------------------------------------------------------------------------
// msg3 v3 (PROVEN, FINAL): persistent grid-stride, 128-edge tiles, 512 thr,
// plain staging. k-paired reduction, 8 consecutive edges x 4 j.
// ---------------------------------------------------------------------------
#define MSG3_ROW 136
#define SM_MSG3_FLOATS (16896 + 128 * MSG3_ROW + 128)
#define SM_MSG3_BYTES (SM_MSG3_FLOATS * 4 + 128 * 4)
__global__ void __launch_bounds__(512) k_msg3(
    const float* __restrict__ f2, const float* __restrict__ ps2,
    const int* __restrict__ bt2, const float* __restrict__ Wp3l,
    const float* __restrict__ b3l, float* __restrict__ agg3, int n) {
    extern __shared__ float sm[];
    float* Wsm = sm;                         // 66*256 = 16896 (k-paired)
    float* ins = Wsm + 16896;                // 128*136
    float* bsm = ins + 128 * MSG3_ROW;       // 128
    int* slots = (int*)(bsm + 128);          // 128
    int tid = threadIdx.x;
    int lane = tid & 31, eg = tid >> 5;      // eg 0..15: edges eg*8..eg*8+7
    for (int t = tid; t < 4224; t += 512)
        *(float4*)&Wsm[4 * t] = *(const float4*)&Wp3l[4 * t];
    if (tid < 128) bsm[tid] = b3l[tid];
    int ntiles = (n + 127) >> 7;
    for (int tile = blockIdx.x; tile < ntiles; tile += gridDim.x) {
        int base = tile << 7;
        __syncthreads();
        for (int idx = tid; idx < 128 * 32; idx += 512) {
            int e = idx >> 5, q = idx & 31;
            int i = base + e;
            if (i >= n) i = n - 1;
            *(float4*)&ins[e * MSG3_ROW + 4 * q] = *(const float4*)&f2[(size_t)i * 128 + 4 * q];
        }
        if (tid < 128) {
            int e = tid;
            int i = base + e;
            if (i >= n) i = n - 1;
            ins[e * MSG3_ROW + 128] = ps2[3 * i];
            ins[e * MSG3_ROW + 129] = ps2[3 * i + 1];
            ins[e * MSG3_ROW + 130] = ps2[3 * i + 2];
            ins[e * MSG3_ROW + 131] = 0.f;
            slots[e] = bt2[i];
        }
        __syncthreads();
        const float* insE = ins + eg * 8 * MSG3_ROW;
        ull acc[8][4];
#pragma unroll
        for (int i = 0; i < 8; i++)
#pragma unroll
            for (int u = 0; u < 4; u++) acc[i][u] = 0ull;
#pragma unroll 2
        for (int k2 = 0; k2 < 66; k2++) {
            ull x[8];
#pragma unroll
            for (int i = 0; i < 8; i++) x[i] = ld2(&insE[i * MSG3_ROW + 2 * k2]);
            const float* wr = &Wsm[k2 * 256 + 2 * lane];
#pragma unroll
            for (int u = 0; u < 4; u++) {
                ull w = ld2(wr + 64 * u);
#pragma unroll
                for (int i = 0; i < 8; i++) ffma2(acc[i][u], x[i], w);
            }
        }
        int gs[8];
#pragma unroll
        for (int i = 0; i < 8; i++) gs[i] = slots[eg * 8 + i];
#pragma unroll
        for (int u = 0; u < 4; u++) {
            int j = lane + 32 * u;
            float bb = bsm[j];
            float v[8];
#pragma unroll
            for (int i = 0; i < 8; i++) v[i] = fmaxf(ull_sum(acc[i][u]) + bb, 0.f);
            int i = 0;
            while (i < 8) {
                int g = gs[i];
                float mv = v[i];
                int f = i + 1;
                while (f < 8 && gs[f] == g) { mv = fmaxf(mv, v[f]); f++; }
                atomicMax((unsigned int*)&agg3[(size_t)g * 128 + j], __float_as_uint(mv));
                i = f;
            }
        }
    }
}

// ------------- fused f3 + head: 8 glimpses/block, 256 threads ---------------
__global__ void __launch_bounds__(256) k_f3head(
    const float* __restrict__ agg3, const float* __restrict__ Wp3g,
    const float* __restrict__ b3g, const float* __restrict__ Wplin,
    const float* __restrict__ blin, const float* __restrict__ eps,
    float* __restrict__ f3, float* __restrict__ out, int G) {
    __shared__ __align__(16) float a3[8 * 128];
    __shared__ __align__(16) float fs[8 * 256];
    __shared__ float sig_s[8 * 128];
    int tid = threadIdx.x;
    int g0 = blockIdx.x * 8;
    {
        int e = tid >> 5, kq = tid & 31;
        int g = g0 + e;
        float4 v = make_float4(0.f, 0.f, 0.f, 0.f);
        if (g < G) v = *(const float4*)&agg3[(size_t)g * 128 + 4 * kq];
        *(float4*)&a3[e * 128 + 4 * kq] = v;
    }
    __syncthreads();
    {
        ull acc[8];
#pragma unroll
        for (int e = 0; e < 8; e++) acc[e] = 0ull;
#pragma unroll 4
        for (int k2 = 0; k2 < 64; k2++) {
            ull w = ld2(&Wp3g[k2 * 512 + 2 * tid]);
#pragma unroll
            for (int e = 0; e < 8; e++) ffma2(acc[e], ld2(&a3[e * 128 + 2 * k2]), w);
        }
        float bb = __ldg(&b3g[tid]);
#pragma unroll
        for (int e = 0; e < 8; e++) {
            int g = g0 + e;
            float vv = celu1(ull_sum(acc[e]) + bb);
            fs[e * 256 + tid] = vv;
            if (g < G) f3[(size_t)g * 256 + tid] = vv;
        }
    }
    __syncthreads();
    ull acc[8];
#pragma unroll
    for (int e = 0; e < 8; e++) acc[e] = 0ull;
#pragma unroll 4
    for (int k2 = 0; k2 < 128; k2++) {
        ull w = ld2(&Wplin[k2 * 512 + 2 * tid]);
#pragma unroll
        for (int e = 0; e < 8; e++) ffma2(acc[e], ld2(&fs[e * 256 + 2 * k2]), w);
    }
    float bb = __ldg(&blin[tid]);
    float val[8];
#pragma unroll
    for (int e = 0; e < 8; e++) val[e] = ull_sum(acc[e]) + bb;
    if (tid >= 128) {
        int j = tid - 128;
#pragma unroll
        for (int e = 0; e < 8; e++) {
            float s = val[e];
            float sg = fmaxf(s, 0.0f) + log1pf(expf(-fabsf(s)));
            sig_s[e * 128 + j] = sg;
            int g = g0 + e;
            if (g < G) out[(size_t)G * 256 + (size_t)g * 128 + j] = sg;
        }
    }
    __syncthreads();
    if (tid < 128) {
        int j = tid;
#pragma unroll
        for (int e = 0; e < 8; e++) {
            int g = g0 + e;
            if (g >= G) continue;
            float mu = val[e];
            float sg = sig_s[e * 128 + j];
            float z = fmaf(sg, eps[(size_t)g * 128 + j], mu);
            out[(size_t)G * 128 + (size_t)g * 128 + j] = mu;
            if (j < 64) out[(size_t)g * 64 + j] = z;
            else out[(size_t)G * 64 + (size_t)g * 64 + (j - 64)] = z;
        }
    }
}

// ---------------------------------------------------------------------------
extern "C" void kernel_launch(void* const* d_in, const int* in_sizes, int n_in,
                              void* d_out, int out_size) {
    const float* rgb = (const float*)d_in[0];
    const float* pos = (const float*)d_in[1];
    const float* W1l = (const float*)d_in[3];
    const float* b1l = (const float*)d_in[4];
    const float* W1g = (const float*)d_in[5];
    const float* b1g = (const float*)d_in[6];
    const float* W2l = (const float*)d_in[7];
    const float* b2l = (const float*)d_in[8];
    const float* W2g = (const float*)d_in[9];
    const float* b2g = (const float*)d_in[10];
    const float* W3l = (const float*)d_in[11];
    const float* b3l = (const float*)d_in[12];
    const float* W3g = (const float*)d_in[13];
    const float* b3g = (const float*)d_in[14];
    const float* Wlin = (const float*)d_in[15];
    const float* blin = (const float*)d_in[16];
    const float* eps = (const float*)d_in[17];
    const int* cl1 = (const int*)d_in[19];
    const int* cl2 = (const int*)d_in[20];
    const int* bt2 = (const int*)d_in[21];

    int N = in_sizes[0];
    int G = in_sizes[2] / 3;
    int M1 = in_sizes[20];
    int M2 = in_sizes[21];
    int P = N / G;

    float* A = nullptr;
    cudaGetSymbolAddress((void**)&A, g_arena);
    size_t o = 0;
    float* f1 = A + o;   o += 32ull * M1;       o = (o + 31) & ~31ull;
    float* ps1 = A + o;  o += 3ull * M1;        o = (o + 31) & ~31ull;
    float* ps2 = A + o;  o += 3ull * M2;        o = (o + 31) & ~31ull;
    float* f2 = A + o;   o += 128ull * M2;      o = (o + 31) & ~31ull;
    float* agg3 = A + o; o += 128ull * G;       o = (o + 31) & ~31ull;
    int* glo1 = (int*)(A + o); o += (size_t)G + 32; o = (o + 31) & ~31ull;
    int* glo2 = (int*)(A + o); o += (size_t)G + 32; o = (o + 31) & ~31ull;
    float* Wp1l = A + o;  o += 64;
    float* Wp1g = A + o;  o += 512;
    float* Wp2l = A + o;  o += 2304;
    float* Wp2g = A + o;  o += 8192;
    float* Wp3g = A + o;  o += 32768;
    float* Wplin = A + o; o += 65536;
    float* Wp3l = A + o;  o += 16896;

    float* out = (float*)d_out;
    float* f3 = out + (size_t)G * 384;

    k_prep<<<(126272 + 32 * G + 255) / 256, 256>>>(W1l, W1g, W2l, W2g, W3g, Wlin, W3l,
                                                   Wp1l, Wp1g, Wp2l, Wp2g, Wp3g,
                                                   Wplin, Wp3l, agg3, G);

    k_stage1<<<G, 512>>>(rgb, pos, cl1, Wp1l, b1l, Wp1g, b1g, ps1, f1, glo1, P, G);

    cudaFuncSetAttribute(k_stage2, cudaFuncAttributeMaxDynamicSharedMemorySize, SMB_BYTES);
    k_stage2<<<296, 512, SMB_BYTES>>>(ps1, f1, cl2, glo1, Wp2l, b2l, Wp2g, b2g,
                                      ps2, f2, glo2, G);

    cudaFuncSetAttribute(k_msg3, cudaFuncAttributeMaxDynamicSharedMemorySize,
                         SM_MSG3_BYTES);
    k_msg3<<<148, 512, SM_MSG3_BYTES>>>(f2, ps2, bt2, Wp3l, b3l, agg3, M2);

    k_f3head<<<(G + 7) / 8, 256>>>(agg3, Wp3g, b3g, Wplin, blin, eps, f3, out, G);
}